// round 1
// baseline (speedup 1.0000x reference)
#include <cuda_runtime.h>
#include <cuda_bf16.h>

// Problem constants (match reference_code)
#define N_NODES  100000
#define N_EDGES  400000
#define N_GRAPHS 2000
#define F_NODE   16
#define F_EDGE   8
#define H1       32
#define H2       16

// ---------------------------------------------------------------------------
// Scratch (device globals; allocation inside kernel_launch is forbidden)
// ---------------------------------------------------------------------------
__device__ float g_U1[(long long)N_NODES * 16 * H1];   // [N,16,32] 204.8 MB
__device__ float g_vb1[N_NODES * H1];                  // x @ B2  (b2 term)
__device__ float g_agg1[N_NODES * H1];
__device__ float g_h1[N_NODES * H1];
__device__ float g_U2[(long long)N_NODES * 16 * H2];   // [N,16,16] 102.4 MB
__device__ float g_vb2[N_NODES * H2];
__device__ float g_agg2[N_NODES * H2];
__device__ float g_h2[N_NODES * H2];
__device__ float g_sums[N_GRAPHS * H2];
__device__ float g_cnts[N_GRAPHS];

// ---------------------------------------------------------------------------
// Zero the accumulators
// ---------------------------------------------------------------------------
__global__ void zero_kernel() {
    int stride = gridDim.x * blockDim.x;
    int t0 = blockIdx.x * blockDim.x + threadIdx.x;
    for (int i = t0; i < N_NODES * H1; i += stride) g_agg1[i] = 0.f;
    for (int i = t0; i < N_NODES * H2; i += stride) g_agg2[i] = 0.f;
    for (int i = t0; i < N_GRAPHS * H2; i += stride) g_sums[i] = 0.f;
    for (int i = t0; i < N_GRAPHS; i += stride) g_cnts[i] = 0.f;
}

// ---------------------------------------------------------------------------
// U1[n, h*32+o] = sum_i x[n,i] * w2[h*512 + i*32 + o]     (h<16, o<32)
// vb1[n, o]     = sum_i x[n,i] * b2[i*32 + o]
// blockDim = 512 (thread c owns output column c), 8-node tiles
// ---------------------------------------------------------------------------
__global__ void u1_kernel(const float* __restrict__ x,
                          const float* __restrict__ w2,
                          const float* __restrict__ b2) {
    __shared__ float sw[16 * 512];   // same layout as global w2 (conflict-free)
    __shared__ float sb2[512];
    __shared__ float sx[8][16];
    int c = threadIdx.x;
    #pragma unroll
    for (int r = 0; r < 16; r++) sw[r * 512 + c] = w2[r * 512 + c];
    sb2[c] = b2[c];
    int h = c >> 5, o = c & 31;
    const int ntiles = N_NODES / 8;  // 12500
    for (int t = blockIdx.x; t < ntiles; t += gridDim.x) {
        __syncthreads();
        if (c < 128) {
            int k = c >> 4, i = c & 15;
            sx[k][i] = x[(t * 8 + k) * 16 + i];
        }
        __syncthreads();
        #pragma unroll
        for (int k = 0; k < 8; k++) {
            int n = t * 8 + k;
            float u = 0.f;
            #pragma unroll
            for (int i = 0; i < 16; i++)
                u += sx[k][i] * sw[h * 512 + i * 32 + o];
            g_U1[(long long)n * 512 + c] = u;
            if (c < 32) {
                float v = 0.f;
                #pragma unroll
                for (int i = 0; i < 16; i++) v += sx[k][i] * sb2[i * 32 + c];
                g_vb1[n * 32 + c] = v;
            }
        }
    }
}

// ---------------------------------------------------------------------------
// U2[n, h*16+o] = sum_i h1[n,i] * w2[h*512 + i*16 + o]    (h<16, o<16, i<32)
// vb2[n, o]     = sum_i h1[n,i] * b2[i*16 + o]
// blockDim = 256; shared w2 padded (stride 528) for conflict-free reads
// ---------------------------------------------------------------------------
__global__ void u2_kernel(const float* __restrict__ w2,
                          const float* __restrict__ b2) {
    __shared__ float sw[16 * 528];
    __shared__ float sb2[512];
    __shared__ float sx[8][32];
    int c = threadIdx.x;  // 0..255
    #pragma unroll
    for (int r = 0; r < 32; r++) {
        int idx = r * 256 + c;
        sw[(idx >> 9) * 528 + (idx & 511)] = w2[idx];
    }
    sb2[c] = b2[c];
    sb2[c + 256] = b2[c + 256];
    int h = c >> 4, o = c & 15;
    const int ntiles = N_NODES / 8;
    for (int t = blockIdx.x; t < ntiles; t += gridDim.x) {
        __syncthreads();
        {
            int k = c >> 5, i = c & 31;
            sx[k][i] = g_h1[(t * 8 + k) * 32 + i];
        }
        __syncthreads();
        #pragma unroll
        for (int k = 0; k < 8; k++) {
            int n = t * 8 + k;
            float u = 0.f;
            #pragma unroll
            for (int i = 0; i < 32; i++)
                u += sx[k][i] * sw[h * 528 + i * 16 + o];
            g_U2[(long long)n * 256 + c] = u;
            if (c < 16) {
                float v = 0.f;
                #pragma unroll
                for (int i = 0; i < 32; i++) v += sx[k][i] * sb2[i * 16 + c];
                g_vb2[n * 16 + c] = v;
            }
        }
    }
}

// ---------------------------------------------------------------------------
// Edge phase conv1: one warp per edge; lane = output channel o (32)
//   a[h] = relu(edge_attr[e] @ w1 + b1)  computed in lanes 0..15
//   msg[o] = vb1[src,o] + sum_h a[h] * U1[src,h,o];  atomicAdd into agg1[dst]
// ---------------------------------------------------------------------------
__global__ void edge1_kernel(const float* __restrict__ edge_attr,
                             const int* __restrict__ ei,
                             const float* __restrict__ w1,
                             const float* __restrict__ b1) {
    __shared__ float w1s[128];
    __shared__ float b1s[16];
    int tid = threadIdx.x;
    if (tid < 128) w1s[tid] = w1[tid];
    if (tid < 16) b1s[tid] = b1[tid];
    __syncthreads();
    int lane = tid & 31;
    int e = blockIdx.x * 8 + (tid >> 5);   // 50000 blocks * 8 warps = 400000
    int src = ei[e];
    int dst = ei[N_EDGES + e];
    float eav = (lane < 8) ? edge_attr[e * 8 + lane] : 0.f;
    float acc = (lane < 16) ? b1s[lane] : 0.f;
    #pragma unroll
    for (int j = 0; j < 8; j++) {
        float ej = __shfl_sync(0xffffffffu, eav, j);
        if (lane < 16) acc += ej * w1s[j * 16 + lane];
    }
    float a = fmaxf(acc, 0.f);
    const float* Up = g_U1 + (long long)src * 512 + lane;
    float msg = g_vb1[src * 32 + lane];
    #pragma unroll
    for (int h = 0; h < 16; h++) {
        float ah = __shfl_sync(0xffffffffu, a, h);
        msg += ah * Up[h * 32];
    }
    atomicAdd(&g_agg1[dst * 32 + lane], msg);
}

// ---------------------------------------------------------------------------
// Edge phase conv2: one warp per 2 edges; half-warp = edge, o = lane&15 (16)
// ---------------------------------------------------------------------------
__global__ void edge2_kernel(const float* __restrict__ edge_attr,
                             const int* __restrict__ ei,
                             const float* __restrict__ w1,
                             const float* __restrict__ b1) {
    __shared__ float w1s[128];
    __shared__ float b1s[16];
    int tid = threadIdx.x;
    if (tid < 128) w1s[tid] = w1[tid];
    if (tid < 16) b1s[tid] = b1[tid];
    __syncthreads();
    int lane = tid & 31;
    int sub = lane >> 4, o = lane & 15;
    int e = (blockIdx.x * 8 + (tid >> 5)) * 2 + sub;  // 25000 blocks
    int src = ei[e];
    int dst = ei[N_EDGES + e];
    float eav = (o < 8) ? edge_attr[e * 8 + o] : 0.f;
    float acc = b1s[o];
    #pragma unroll
    for (int j = 0; j < 8; j++) {
        float ej = __shfl_sync(0xffffffffu, eav, sub * 16 + j);
        acc += ej * w1s[j * 16 + o];
    }
    float a = fmaxf(acc, 0.f);
    const float* Up = g_U2 + (long long)src * 256 + o;
    float msg = g_vb2[src * 16 + o];
    #pragma unroll
    for (int h = 0; h < 16; h++) {
        float ah = __shfl_sync(0xffffffffu, a, sub * 16 + h);
        msg += ah * Up[h * 16];
    }
    atomicAdd(&g_agg2[dst * 16 + o], msg);
}

// ---------------------------------------------------------------------------
// Node updates: h = relu(x @ root + agg + bias)
// ---------------------------------------------------------------------------
__global__ void node1_kernel(const float* __restrict__ x,
                             const float* __restrict__ root1,
                             const float* __restrict__ bias1) {
    int idx = blockIdx.x * blockDim.x + threadIdx.x;
    if (idx >= N_NODES * 32) return;
    int n = idx >> 5, o = idx & 31;
    float acc = g_agg1[idx] + bias1[o];
    const float* xr = x + n * 16;
    #pragma unroll
    for (int i = 0; i < 16; i++) acc += xr[i] * root1[i * 32 + o];
    g_h1[idx] = fmaxf(acc, 0.f);
}

__global__ void node2_kernel(const float* __restrict__ root2,
                             const float* __restrict__ bias2) {
    int idx = blockIdx.x * blockDim.x + threadIdx.x;
    if (idx >= N_NODES * 16) return;
    int n = idx >> 4, o = idx & 15;
    float acc = g_agg2[idx] + bias2[o];
    const float* hr = g_h1 + n * 32;
    #pragma unroll
    for (int i = 0; i < 32; i++) acc += hr[i] * root2[i * 16 + o];
    g_h2[idx] = fmaxf(acc, 0.f);
}

// ---------------------------------------------------------------------------
// Global mean pool (batch is sorted; atomic contention per graph is modest)
// ---------------------------------------------------------------------------
__global__ void pool_kernel(const int* __restrict__ batch) {
    int idx = blockIdx.x * blockDim.x + threadIdx.x;
    if (idx >= N_NODES * 16) return;
    int n = idx >> 4, o = idx & 15;
    int g = batch[n];
    atomicAdd(&g_sums[g * 16 + o], g_h2[idx]);
    if (o == 0) atomicAdd(&g_cnts[g], 1.0f);
}

// ---------------------------------------------------------------------------
// Readout MLP: 16 -> 8 (relu) -> 1, one thread per graph
// ---------------------------------------------------------------------------
__global__ void readout_kernel(const float* __restrict__ lin1_w,
                               const float* __restrict__ lin1_b,
                               const float* __restrict__ lin2_w,
                               const float* __restrict__ lin2_b,
                               float* __restrict__ out) {
    int g = blockIdx.x * blockDim.x + threadIdx.x;
    if (g >= N_GRAPHS) return;
    float inv = 1.0f / fmaxf(g_cnts[g], 1.0f);
    float p[16];
    #pragma unroll
    for (int c = 0; c < 16; c++) p[c] = g_sums[g * 16 + c] * inv;
    float o = lin2_b[0];
    #pragma unroll
    for (int j = 0; j < 8; j++) {
        float z = lin1_b[j];
        #pragma unroll
        for (int c = 0; c < 16; c++) z += p[c] * lin1_w[c * 8 + j];
        o += fmaxf(z, 0.f) * lin2_w[j];
    }
    out[g] = o;
}

// ---------------------------------------------------------------------------
// Launch
// ---------------------------------------------------------------------------
extern "C" void kernel_launch(void* const* d_in, const int* in_sizes, int n_in,
                              void* d_out, int out_size) {
    const float* x         = (const float*)d_in[0];
    const float* edge_attr = (const float*)d_in[1];
    const int*   ei        = (const int*)  d_in[2];
    const int*   batch     = (const int*)  d_in[3];
    const float* nn1_w1    = (const float*)d_in[4];
    const float* nn1_b1    = (const float*)d_in[5];
    const float* nn1_w2    = (const float*)d_in[6];
    const float* nn1_b2    = (const float*)d_in[7];
    const float* root1     = (const float*)d_in[8];
    const float* bias1     = (const float*)d_in[9];
    const float* nn2_w1    = (const float*)d_in[10];
    const float* nn2_b1    = (const float*)d_in[11];
    const float* nn2_w2    = (const float*)d_in[12];
    const float* nn2_b2    = (const float*)d_in[13];
    const float* root2     = (const float*)d_in[14];
    const float* bias2     = (const float*)d_in[15];
    const float* lin1_w    = (const float*)d_in[16];
    const float* lin1_b    = (const float*)d_in[17];
    const float* lin2_w    = (const float*)d_in[18];
    const float* lin2_b    = (const float*)d_in[19];
    float* out = (float*)d_out;

    zero_kernel<<<2048, 256>>>();
    u1_kernel<<<640, 512>>>(x, nn1_w2, nn1_b2);
    edge1_kernel<<<N_EDGES / 8, 256>>>(edge_attr, ei, nn1_w1, nn1_b1);
    node1_kernel<<<(N_NODES * 32) / 256, 256>>>(x, root1, bias1);
    u2_kernel<<<640, 256>>>(nn2_w2, nn2_b2);
    edge2_kernel<<<N_EDGES / 16, 256>>>(edge_attr, ei, nn2_w1, nn2_b1);
    node2_kernel<<<(N_NODES * 16) / 256, 256>>>(root2, bias2);
    pool_kernel<<<(N_NODES * 16) / 256, 256>>>(batch);
    readout_kernel<<<(N_GRAPHS + 255) / 256, 256>>>(lin1_w, lin1_b, lin2_w, lin2_b, out);
}

// round 2
// speedup vs baseline: 1.2104x; 1.2104x over previous
#include <cuda_runtime.h>
#include <cuda_fp16.h>

// Problem constants (match reference_code)
#define N_NODES  100000
#define N_EDGES  400000
#define N_GRAPHS 2000
#define F_NODE   16
#define F_EDGE   8
#define H1       32
#define H2       16

// ---------------------------------------------------------------------------
// Scratch (device globals; allocation inside kernel_launch is forbidden)
// ---------------------------------------------------------------------------
__device__ __half g_U1h[(long long)N_NODES * 16 * H1];  // [N,16,32] fp16, 102.4 MB
__device__ float  g_vb1[N_NODES * H1];                  // x @ B2 (b2 term)
__device__ float  g_agg1[N_NODES * H1];
__device__ float  g_h1[N_NODES * H1];
__device__ __half g_U2h[(long long)N_NODES * 16 * H2];  // [N,16,16] fp16, 51.2 MB
__device__ float  g_vb2[N_NODES * H2];
__device__ float  g_agg2[N_NODES * H2];
__device__ float  g_sums[N_GRAPHS * H2];
__device__ float  g_cnts[N_GRAPHS];

// ---------------------------------------------------------------------------
// Zero the accumulators
// ---------------------------------------------------------------------------
__global__ void zero_kernel() {
    int stride = gridDim.x * blockDim.x;
    int t0 = blockIdx.x * blockDim.x + threadIdx.x;
    for (int i = t0; i < N_NODES * H1; i += stride) g_agg1[i] = 0.f;
    for (int i = t0; i < N_NODES * H2; i += stride) g_agg2[i] = 0.f;
    for (int i = t0; i < N_GRAPHS * H2; i += stride) g_sums[i] = 0.f;
    for (int i = t0; i < N_GRAPHS; i += stride) g_cnts[i] = 0.f;
}

// ---------------------------------------------------------------------------
// U1[n, h*32+o] = sum_i x[n,i] * w2[h*512 + i*32 + o]     (h<16, o<32)
// vb1[n, o]     = sum_i x[n,i] * b2[i*32 + o]
// blockDim = 512 (thread c owns output column c), 8-node tiles
// ---------------------------------------------------------------------------
__global__ void u1_kernel(const float* __restrict__ x,
                          const float* __restrict__ w2,
                          const float* __restrict__ b2) {
    __shared__ float sw[16 * 512];   // same layout as global w2 (conflict-free)
    __shared__ float sb2[512];
    __shared__ float sx[8][16];
    int c = threadIdx.x;
    #pragma unroll
    for (int r = 0; r < 16; r++) sw[r * 512 + c] = w2[r * 512 + c];
    sb2[c] = b2[c];
    int h = c >> 5, o = c & 31;
    const int ntiles = N_NODES / 8;  // 12500
    for (int t = blockIdx.x; t < ntiles; t += gridDim.x) {
        __syncthreads();
        if (c < 128) {
            int k = c >> 4, i = c & 15;
            sx[k][i] = x[(t * 8 + k) * 16 + i];
        }
        __syncthreads();
        #pragma unroll
        for (int k = 0; k < 8; k++) {
            int n = t * 8 + k;
            float u = 0.f;
            #pragma unroll
            for (int i = 0; i < 16; i++)
                u += sx[k][i] * sw[h * 512 + i * 32 + o];
            g_U1h[(long long)n * 512 + c] = __float2half(u);
            if (c < 32) {
                float v = 0.f;
                #pragma unroll
                for (int i = 0; i < 16; i++) v += sx[k][i] * sb2[i * 32 + c];
                g_vb1[n * 32 + c] = v;
            }
        }
    }
}

// ---------------------------------------------------------------------------
// U2[n, h*16+o] = sum_i h1[n,i] * w2[h*512 + i*16 + o]    (h<16, o<16, i<32)
// vb2[n, o]     = sum_i h1[n,i] * b2[i*16 + o]
// blockDim = 256; shared w2 padded (stride 528) for conflict-free reads
// ---------------------------------------------------------------------------
__global__ void u2_kernel(const float* __restrict__ w2,
                          const float* __restrict__ b2) {
    __shared__ float sw[16 * 528];
    __shared__ float sb2[512];
    __shared__ float sx[8][32];
    int c = threadIdx.x;  // 0..255
    #pragma unroll
    for (int r = 0; r < 32; r++) {
        int idx = r * 256 + c;
        sw[(idx >> 9) * 528 + (idx & 511)] = w2[idx];
    }
    sb2[c] = b2[c];
    sb2[c + 256] = b2[c + 256];
    int h = c >> 4, o = c & 15;
    const int ntiles = N_NODES / 8;
    for (int t = blockIdx.x; t < ntiles; t += gridDim.x) {
        __syncthreads();
        {
            int k = c >> 5, i = c & 31;
            sx[k][i] = g_h1[(t * 8 + k) * 32 + i];
        }
        __syncthreads();
        #pragma unroll
        for (int k = 0; k < 8; k++) {
            int n = t * 8 + k;
            float u = 0.f;
            #pragma unroll
            for (int i = 0; i < 32; i++)
                u += sx[k][i] * sw[h * 528 + i * 16 + o];
            g_U2h[(long long)n * 256 + c] = __float2half(u);
            if (c < 16) {
                float v = 0.f;
                #pragma unroll
                for (int i = 0; i < 32; i++) v += sx[k][i] * sb2[i * 16 + c];
                g_vb2[n * 16 + c] = v;
            }
        }
    }
}

// ---------------------------------------------------------------------------
// Edge phase conv1: warp handles 2 edges; half-warp per edge; each lane owns
// an output half2 pair (oh = lane&15 -> outputs 2oh, 2oh+1).
//   a[h] = relu(edge_attr[e] @ w1 + b1)   (lane oh owns hidden channel oh)
//   msg = vb1[src] + sum_h a[h] * U1h[src,h,:] ; atomicAdd into agg1[dst]
// ---------------------------------------------------------------------------
__global__ void __launch_bounds__(256) edge1_kernel(
        const float* __restrict__ edge_attr,
        const int* __restrict__ ei,
        const float* __restrict__ w1,
        const float* __restrict__ b1) {
    __shared__ float w1s[128];
    __shared__ float b1s[16];
    int tid = threadIdx.x;
    if (tid < 128) w1s[tid] = w1[tid];
    if (tid < 16) b1s[tid] = b1[tid];
    __syncthreads();
    int lane = tid & 31;
    int sub = lane >> 4, oh = lane & 15;
    int w = blockIdx.x * 8 + (tid >> 5);      // 25000 blocks * 8 warps
    int e = w * 2 + sub;
    int src = ei[e];
    int dst = ei[N_EDGES + e];
    float eav = (oh < 8) ? edge_attr[e * 8 + oh] : 0.f;
    float acc = b1s[oh];
    #pragma unroll
    for (int j = 0; j < 8; j++) {
        float ej = __shfl_sync(0xffffffffu, eav, sub * 16 + j);
        acc += ej * w1s[j * 16 + oh];
    }
    float a = fmaxf(acc, 0.f);
    const __half2* Up = (const __half2*)(g_U1h + (long long)src * 512) + oh;
    float2 vb = ((const float2*)g_vb1)[src * 16 + oh];
    float m0 = vb.x, m1 = vb.y;
    #pragma unroll
    for (int h = 0; h < 16; h++) {
        float ah = __shfl_sync(0xffffffffu, a, sub * 16 + h);
        float2 u = __half22float2(Up[h * 16]);
        m0 += ah * u.x;
        m1 += ah * u.y;
    }
    atomicAdd(&g_agg1[dst * 32 + 2 * oh], m0);
    atomicAdd(&g_agg1[dst * 32 + 2 * oh + 1], m1);
}

// ---------------------------------------------------------------------------
// Edge phase conv2: warp handles 4 edges; 8 lanes per edge; each lane owns
// an output half2 (oh = lane&7 -> outputs 2oh, 2oh+1) and 2 hidden channels.
// ---------------------------------------------------------------------------
__global__ void __launch_bounds__(256) edge2_kernel(
        const float* __restrict__ edge_attr,
        const int* __restrict__ ei,
        const float* __restrict__ w1,
        const float* __restrict__ b1) {
    __shared__ float w1s[128];
    __shared__ float b1s[16];
    int tid = threadIdx.x;
    if (tid < 128) w1s[tid] = w1[tid];
    if (tid < 16) b1s[tid] = b1[tid];
    __syncthreads();
    int lane = tid & 31;
    int sub = lane >> 3, oh = lane & 7;
    int w = blockIdx.x * 8 + (tid >> 5);      // 12500 blocks * 8 warps
    int e = w * 4 + sub;
    int src = ei[e];
    int dst = ei[N_EDGES + e];
    float eav = edge_attr[e * 8 + oh];         // all 8 lanes load an attr
    float acc0 = b1s[oh];
    float acc1 = b1s[oh + 8];
    #pragma unroll
    for (int j = 0; j < 8; j++) {
        float ej = __shfl_sync(0xffffffffu, eav, sub * 8 + j);
        acc0 += ej * w1s[j * 16 + oh];
        acc1 += ej * w1s[j * 16 + oh + 8];
    }
    float a0 = fmaxf(acc0, 0.f);   // hidden channels oh and oh+8
    float a1 = fmaxf(acc1, 0.f);
    const __half2* Up = (const __half2*)(g_U2h + (long long)src * 256) + oh;
    float2 vb = ((const float2*)g_vb2)[src * 8 + oh];
    float m0 = vb.x, m1 = vb.y;
    #pragma unroll
    for (int h = 0; h < 16; h++) {
        float ah = (h < 8) ? __shfl_sync(0xffffffffu, a0, sub * 8 + h)
                           : __shfl_sync(0xffffffffu, a1, sub * 8 + h - 8);
        float2 u = __half22float2(Up[h * 8]);
        m0 += ah * u.x;
        m1 += ah * u.y;
    }
    atomicAdd(&g_agg2[dst * 16 + 2 * oh], m0);
    atomicAdd(&g_agg2[dst * 16 + 2 * oh + 1], m1);
}

// ---------------------------------------------------------------------------
// Node update 1: h1 = relu(x @ root1 + agg1 + bias1)
// ---------------------------------------------------------------------------
__global__ void node1_kernel(const float* __restrict__ x,
                             const float* __restrict__ root1,
                             const float* __restrict__ bias1) {
    int idx = blockIdx.x * blockDim.x + threadIdx.x;
    if (idx >= N_NODES * 32) return;
    int n = idx >> 5, o = idx & 31;
    float acc = g_agg1[idx] + bias1[o];
    const float* xr = x + n * 16;
    #pragma unroll
    for (int i = 0; i < 16; i++) acc += xr[i] * root1[i * 32 + o];
    g_h1[idx] = fmaxf(acc, 0.f);
}

// ---------------------------------------------------------------------------
// Node update 2 fused with global mean-pool accumulation
// ---------------------------------------------------------------------------
__global__ void node2pool_kernel(const float* __restrict__ root2,
                                 const float* __restrict__ bias2,
                                 const int* __restrict__ batch) {
    int idx = blockIdx.x * blockDim.x + threadIdx.x;
    if (idx >= N_NODES * 16) return;
    int n = idx >> 4, o = idx & 15;
    float acc = g_agg2[idx] + bias2[o];
    const float* hr = g_h1 + n * 32;
    #pragma unroll
    for (int i = 0; i < 32; i++) acc += hr[i] * root2[i * 16 + o];
    float h = fmaxf(acc, 0.f);
    int g = batch[n];
    atomicAdd(&g_sums[g * 16 + o], h);
    if (o == 0) atomicAdd(&g_cnts[g], 1.0f);
}

// ---------------------------------------------------------------------------
// Readout MLP: 16 -> 8 (relu) -> 1, one thread per graph
// ---------------------------------------------------------------------------
__global__ void readout_kernel(const float* __restrict__ lin1_w,
                               const float* __restrict__ lin1_b,
                               const float* __restrict__ lin2_w,
                               const float* __restrict__ lin2_b,
                               float* __restrict__ out) {
    int g = blockIdx.x * blockDim.x + threadIdx.x;
    if (g >= N_GRAPHS) return;
    float inv = 1.0f / fmaxf(g_cnts[g], 1.0f);
    float p[16];
    #pragma unroll
    for (int c = 0; c < 16; c++) p[c] = g_sums[g * 16 + c] * inv;
    float o = lin2_b[0];
    #pragma unroll
    for (int j = 0; j < 8; j++) {
        float z = lin1_b[j];
        #pragma unroll
        for (int c = 0; c < 16; c++) z += p[c] * lin1_w[c * 8 + j];
        o += fmaxf(z, 0.f) * lin2_w[j];
    }
    out[g] = o;
}

// ---------------------------------------------------------------------------
// Launch
// ---------------------------------------------------------------------------
extern "C" void kernel_launch(void* const* d_in, const int* in_sizes, int n_in,
                              void* d_out, int out_size) {
    const float* x         = (const float*)d_in[0];
    const float* edge_attr = (const float*)d_in[1];
    const int*   ei        = (const int*)  d_in[2];
    const int*   batch     = (const int*)  d_in[3];
    const float* nn1_w1    = (const float*)d_in[4];
    const float* nn1_b1    = (const float*)d_in[5];
    const float* nn1_w2    = (const float*)d_in[6];
    const float* nn1_b2    = (const float*)d_in[7];
    const float* root1     = (const float*)d_in[8];
    const float* bias1     = (const float*)d_in[9];
    const float* nn2_w1    = (const float*)d_in[10];
    const float* nn2_b1    = (const float*)d_in[11];
    const float* nn2_w2    = (const float*)d_in[12];
    const float* nn2_b2    = (const float*)d_in[13];
    const float* root2     = (const float*)d_in[14];
    const float* bias2     = (const float*)d_in[15];
    const float* lin1_w    = (const float*)d_in[16];
    const float* lin1_b    = (const float*)d_in[17];
    const float* lin2_w    = (const float*)d_in[18];
    const float* lin2_b    = (const float*)d_in[19];
    float* out = (float*)d_out;

    zero_kernel<<<2048, 256>>>();
    u1_kernel<<<640, 512>>>(x, nn1_w2, nn1_b2);
    edge1_kernel<<<N_EDGES / 16, 256>>>(edge_attr, ei, nn1_w1, nn1_b1);
    node1_kernel<<<(N_NODES * 32) / 256, 256>>>(x, root1, bias1);
    u2_kernel<<<640, 256>>>(nn2_w2, nn2_b2);
    edge2_kernel<<<N_EDGES / 32, 256>>>(edge_attr, ei, nn2_w1, nn2_b1);
    node2pool_kernel<<<(N_NODES * 16) / 256, 256>>>(root2, bias2, batch);
    readout_kernel<<<(N_GRAPHS + 255) / 256, 256>>>(lin1_w, lin1_b, lin2_w, lin2_b, out);
}

// round 13
// speedup vs baseline: 1.3473x; 1.1132x over previous
#include <cuda_runtime.h>
#include <cuda_fp16.h>

#define N_NODES  100000
#define N_EDGES  400000
#define N_GRAPHS 2000

// ---------------------------------------------------------------------------
// Scratch
// ---------------------------------------------------------------------------
__device__ __half g_U1x[(long long)N_NODES * 18 * 32];  // rows 0-15: U, 16: vb, 17: 0  (115 MB)
__device__ __half g_U2x[(long long)N_NODES * 18 * 16];  // (57.6 MB)
__device__ __half g_A1h[(long long)N_EDGES * 16];       // edge-MLP activations conv1 (12.8 MB)
__device__ __half g_A2h[(long long)N_EDGES * 16];       // conv2
__device__ float  g_agg1[N_NODES * 32];
__device__ float  g_h1[N_NODES * 32];
__device__ float  g_agg2[N_NODES * 16];
__device__ float  g_sums[N_GRAPHS * 16];
__device__ float  g_cnts[N_GRAPHS];

__device__ __forceinline__ unsigned h2u(__half2 h) {
    return *reinterpret_cast<unsigned*>(&h);
}

// ---------------------------------------------------------------------------
// Prep: compute A1/A2 (relu(edge_attr@w1+b1)) in fp16, and zero accumulators.
// One thread per edge.
// ---------------------------------------------------------------------------
__global__ void __launch_bounds__(256) prep_kernel(
        const float* __restrict__ edge_attr,
        const float* __restrict__ w1a, const float* __restrict__ b1a,
        const float* __restrict__ w1b, const float* __restrict__ b1b) {
    int t = blockIdx.x * 256 + threadIdx.x;
    if (t < N_EDGES) {
        float4 e0 = ((const float4*)edge_attr)[t * 2];
        float4 e1 = ((const float4*)edge_attr)[t * 2 + 1];
        float ea[8] = {e0.x, e0.y, e0.z, e0.w, e1.x, e1.y, e1.z, e1.w};
        // ---- MLP for conv1 ----
        {
            float s[16];
            #pragma unroll
            for (int q = 0; q < 4; q++) {
                float4 b = ((const float4*)b1a)[q];
                s[4*q] = b.x; s[4*q+1] = b.y; s[4*q+2] = b.z; s[4*q+3] = b.w;
            }
            #pragma unroll
            for (int j = 0; j < 8; j++) {
                #pragma unroll
                for (int q = 0; q < 4; q++) {
                    float4 w = ((const float4*)w1a)[j * 4 + q];
                    s[4*q]   += ea[j] * w.x;
                    s[4*q+1] += ea[j] * w.y;
                    s[4*q+2] += ea[j] * w.z;
                    s[4*q+3] += ea[j] * w.w;
                }
            }
            uint4 o0, o1;
            __half2 p;
            p = __floats2half2_rn(fmaxf(s[0],0.f),  fmaxf(s[1],0.f));  o0.x = h2u(p);
            p = __floats2half2_rn(fmaxf(s[2],0.f),  fmaxf(s[3],0.f));  o0.y = h2u(p);
            p = __floats2half2_rn(fmaxf(s[4],0.f),  fmaxf(s[5],0.f));  o0.z = h2u(p);
            p = __floats2half2_rn(fmaxf(s[6],0.f),  fmaxf(s[7],0.f));  o0.w = h2u(p);
            p = __floats2half2_rn(fmaxf(s[8],0.f),  fmaxf(s[9],0.f));  o1.x = h2u(p);
            p = __floats2half2_rn(fmaxf(s[10],0.f), fmaxf(s[11],0.f)); o1.y = h2u(p);
            p = __floats2half2_rn(fmaxf(s[12],0.f), fmaxf(s[13],0.f)); o1.z = h2u(p);
            p = __floats2half2_rn(fmaxf(s[14],0.f), fmaxf(s[15],0.f)); o1.w = h2u(p);
            ((uint4*)g_A1h)[t * 2]     = o0;
            ((uint4*)g_A1h)[t * 2 + 1] = o1;
        }
        // ---- MLP for conv2 ----
        {
            float s[16];
            #pragma unroll
            for (int q = 0; q < 4; q++) {
                float4 b = ((const float4*)b1b)[q];
                s[4*q] = b.x; s[4*q+1] = b.y; s[4*q+2] = b.z; s[4*q+3] = b.w;
            }
            #pragma unroll
            for (int j = 0; j < 8; j++) {
                #pragma unroll
                for (int q = 0; q < 4; q++) {
                    float4 w = ((const float4*)w1b)[j * 4 + q];
                    s[4*q]   += ea[j] * w.x;
                    s[4*q+1] += ea[j] * w.y;
                    s[4*q+2] += ea[j] * w.z;
                    s[4*q+3] += ea[j] * w.w;
                }
            }
            uint4 o0, o1;
            __half2 p;
            p = __floats2half2_rn(fmaxf(s[0],0.f),  fmaxf(s[1],0.f));  o0.x = h2u(p);
            p = __floats2half2_rn(fmaxf(s[2],0.f),  fmaxf(s[3],0.f));  o0.y = h2u(p);
            p = __floats2half2_rn(fmaxf(s[4],0.f),  fmaxf(s[5],0.f));  o0.z = h2u(p);
            p = __floats2half2_rn(fmaxf(s[6],0.f),  fmaxf(s[7],0.f));  o0.w = h2u(p);
            p = __floats2half2_rn(fmaxf(s[8],0.f),  fmaxf(s[9],0.f));  o1.x = h2u(p);
            p = __floats2half2_rn(fmaxf(s[10],0.f), fmaxf(s[11],0.f)); o1.y = h2u(p);
            p = __floats2half2_rn(fmaxf(s[12],0.f), fmaxf(s[13],0.f)); o1.z = h2u(p);
            p = __floats2half2_rn(fmaxf(s[14],0.f), fmaxf(s[15],0.f)); o1.w = h2u(p);
            ((uint4*)g_A2h)[t * 2]     = o0;
            ((uint4*)g_A2h)[t * 2 + 1] = o1;
        }
    }
    // ---- zero accumulators (grid-stride) ----
    int nt = gridDim.x * 256;
    float4 z4 = make_float4(0.f, 0.f, 0.f, 0.f);
    for (int i = t; i < N_NODES * 32 / 4; i += nt) ((float4*)g_agg1)[i] = z4;
    for (int i = t; i < N_NODES * 16 / 4; i += nt) ((float4*)g_agg2)[i] = z4;
    for (int i = t; i < N_GRAPHS * 16 / 4; i += nt) ((float4*)g_sums)[i] = z4;
    for (int i = t; i < N_GRAPHS; i += nt) g_cnts[i] = 0.f;
}

// ---------------------------------------------------------------------------
// U1[n, h*32+o] = sum_i x[n,i] * w2[h*512 + i*32 + o]  ; rows 16=vb, 17=0
// block 512; thread c owns column c (h=c>>5, o=c&31); weights in registers.
// ---------------------------------------------------------------------------
__global__ void __launch_bounds__(512) u1_kernel(
        const float* __restrict__ x,
        const float* __restrict__ w2,
        const float* __restrict__ b2) {
    int c = threadIdx.x;
    int h = c >> 5, o = c & 31;
    float wreg[16];
    #pragma unroll
    for (int i = 0; i < 16; i++) wreg[i] = w2[h * 512 + i * 32 + o];
    float breg[16];
    #pragma unroll
    for (int i = 0; i < 16; i++) breg[i] = (c < 32) ? b2[i * 32 + o] : 0.f;
    __shared__ float sx[8][16];
    const int ntiles = N_NODES / 8;
    for (int t = blockIdx.x; t < ntiles; t += gridDim.x) {
        __syncthreads();
        if (c < 32) ((float4*)sx)[c] = ((const float4*)x)[t * 32 + c];
        __syncthreads();
        #pragma unroll
        for (int k = 0; k < 8; k++) {
            const float4* xk = (const float4*)sx[k];
            float4 a0 = xk[0], a1 = xk[1], a2 = xk[2], a3 = xk[3];
            float xv[16] = {a0.x,a0.y,a0.z,a0.w, a1.x,a1.y,a1.z,a1.w,
                            a2.x,a2.y,a2.z,a2.w, a3.x,a3.y,a3.z,a3.w};
            float u = 0.f;
            #pragma unroll
            for (int i = 0; i < 16; i++) u += xv[i] * wreg[i];
            long long n = (long long)(t * 8 + k);
            g_U1x[n * 576 + c] = __float2half(u);
            if (c < 32) {
                float v = 0.f;
                #pragma unroll
                for (int i = 0; i < 16; i++) v += xv[i] * breg[i];
                g_U1x[n * 576 + 512 + c] = __float2half(v);
                g_U1x[n * 576 + 544 + c] = __float2half(0.f);
            }
        }
    }
}

// ---------------------------------------------------------------------------
// U2[n, h*16+o] = sum_i h1[n,i] * w2[h*512 + i*16 + o] ; rows 16=vb, 17=0
// block 256; h=c>>4, o=c&15; weights in registers.
// ---------------------------------------------------------------------------
__global__ void __launch_bounds__(256) u2_kernel(
        const float* __restrict__ w2,
        const float* __restrict__ b2) {
    int c = threadIdx.x;
    int h = c >> 4, o = c & 15;
    float wreg[32];
    #pragma unroll
    for (int i = 0; i < 32; i++) wreg[i] = w2[h * 512 + i * 16 + o];
    float breg[32];
    #pragma unroll
    for (int i = 0; i < 32; i++) breg[i] = (c < 16) ? b2[i * 16 + o] : 0.f;
    __shared__ float sh[8][32];
    const int ntiles = N_NODES / 8;
    for (int t = blockIdx.x; t < ntiles; t += gridDim.x) {
        __syncthreads();
        if (c < 64) ((float4*)sh)[c] = ((const float4*)g_h1)[t * 64 + c];
        __syncthreads();
        #pragma unroll
        for (int k = 0; k < 8; k++) {
            const float4* hk = (const float4*)sh[k];
            float hv[32];
            #pragma unroll
            for (int q = 0; q < 8; q++) {
                float4 a = hk[q];
                hv[4*q] = a.x; hv[4*q+1] = a.y; hv[4*q+2] = a.z; hv[4*q+3] = a.w;
            }
            float u = 0.f;
            #pragma unroll
            for (int i = 0; i < 32; i++) u += hv[i] * wreg[i];
            long long n = (long long)(t * 8 + k);
            g_U2x[n * 288 + c] = __float2half(u);
            if (c < 16) {
                float v = 0.f;
                #pragma unroll
                for (int i = 0; i < 32; i++) v += hv[i] * breg[i];
                g_U2x[n * 288 + 256 + c] = __float2half(v);
                g_U2x[n * 288 + 272 + c] = __float2half(0.f);
            }
        }
    }
}

// ---------------------------------------------------------------------------
// Edge conv1: one warp per edge. Lane l reads half2 (outputs 2(l&15), 2(l&15)+1)
// of row 2p (l<16) or 2p+1 (l>=16). Coefficients from A1 (one uniform LDG.128x2).
// ---------------------------------------------------------------------------
__global__ void __launch_bounds__(256) edge1_kernel(const int* __restrict__ ei) {
    int tid = threadIdx.x;
    int lane = tid & 31;
    int e = blockIdx.x * 8 + (tid >> 5);
    int src = ei[e];
    int dst = ei[N_EDGES + e];
    uint4 q0 = ((const uint4*)g_A1h)[e * 2];
    uint4 q1 = ((const uint4*)g_A1h)[e * 2 + 1];
    float f[16];
    {
        float2 t;
        t = __half22float2(*(__half2*)&q0.x); f[0]=t.x; f[1]=t.y;
        t = __half22float2(*(__half2*)&q0.y); f[2]=t.x; f[3]=t.y;
        t = __half22float2(*(__half2*)&q0.z); f[4]=t.x; f[5]=t.y;
        t = __half22float2(*(__half2*)&q0.w); f[6]=t.x; f[7]=t.y;
        t = __half22float2(*(__half2*)&q1.x); f[8]=t.x; f[9]=t.y;
        t = __half22float2(*(__half2*)&q1.y); f[10]=t.x; f[11]=t.y;
        t = __half22float2(*(__half2*)&q1.z); f[12]=t.x; f[13]=t.y;
        t = __half22float2(*(__half2*)&q1.w); f[14]=t.x; f[15]=t.y;
    }
    bool odd = lane >= 16;
    float cf[9];
    #pragma unroll
    for (int p = 0; p < 8; p++) cf[p] = odd ? f[2*p+1] : f[2*p];
    cf[8] = odd ? 0.f : 1.f;
    const __half2* Uv = (const __half2*)g_U1x + (long long)src * 288 + lane;
    float m0 = 0.f, m1 = 0.f;
    #pragma unroll
    for (int p = 0; p < 9; p++) {
        float2 u = __half22float2(Uv[p * 32]);
        m0 += cf[p] * u.x;
        m1 += cf[p] * u.y;
    }
    m0 += __shfl_xor_sync(0xffffffffu, m0, 16);
    m1 += __shfl_xor_sync(0xffffffffu, m1, 16);
    if (lane < 16) {
        float* addr = &g_agg1[dst * 32 + 2 * lane];
        asm volatile("red.global.add.v2.f32 [%0], {%1, %2};"
                     :: "l"(addr), "f"(m0), "f"(m1) : "memory");
    }
}

// ---------------------------------------------------------------------------
// Edge conv2: warp = 2 edges (half-warp each). Lane hl=l&15 reads half2
// (outputs 2(hl&7), +1) of row 2p (hl<8) or 2p+1 (hl>=8).
// ---------------------------------------------------------------------------
__global__ void __launch_bounds__(256) edge2_kernel(const int* __restrict__ ei) {
    int tid = threadIdx.x;
    int lane = tid & 31;
    int hw = lane >> 4, hl = lane & 15;
    int e = (blockIdx.x * 8 + (tid >> 5)) * 2 + hw;
    int src = ei[e];
    int dst = ei[N_EDGES + e];
    uint4 q0 = ((const uint4*)g_A2h)[e * 2];
    uint4 q1 = ((const uint4*)g_A2h)[e * 2 + 1];
    float f[16];
    {
        float2 t;
        t = __half22float2(*(__half2*)&q0.x); f[0]=t.x; f[1]=t.y;
        t = __half22float2(*(__half2*)&q0.y); f[2]=t.x; f[3]=t.y;
        t = __half22float2(*(__half2*)&q0.z); f[4]=t.x; f[5]=t.y;
        t = __half22float2(*(__half2*)&q0.w); f[6]=t.x; f[7]=t.y;
        t = __half22float2(*(__half2*)&q1.x); f[8]=t.x; f[9]=t.y;
        t = __half22float2(*(__half2*)&q1.y); f[10]=t.x; f[11]=t.y;
        t = __half22float2(*(__half2*)&q1.z); f[12]=t.x; f[13]=t.y;
        t = __half22float2(*(__half2*)&q1.w); f[14]=t.x; f[15]=t.y;
    }
    bool odd = hl >= 8;
    float cf[9];
    #pragma unroll
    for (int p = 0; p < 8; p++) cf[p] = odd ? f[2*p+1] : f[2*p];
    cf[8] = odd ? 0.f : 1.f;
    const __half2* Uv = (const __half2*)g_U2x + (long long)src * 144 + hl;
    float m0 = 0.f, m1 = 0.f;
    #pragma unroll
    for (int p = 0; p < 9; p++) {
        float2 u = __half22float2(Uv[p * 16]);
        m0 += cf[p] * u.x;
        m1 += cf[p] * u.y;
    }
    m0 += __shfl_xor_sync(0xffffffffu, m0, 8);
    m1 += __shfl_xor_sync(0xffffffffu, m1, 8);
    if (hl < 8) {
        float* addr = &g_agg2[dst * 16 + 2 * hl];
        asm volatile("red.global.add.v2.f32 [%0], {%1, %2};"
                     :: "l"(addr), "f"(m0), "f"(m1) : "memory");
    }
}

// ---------------------------------------------------------------------------
// Node update 1: h1 = relu(x @ root1 + agg1 + bias1); block = 8 nodes x 32 o
// ---------------------------------------------------------------------------
__global__ void __launch_bounds__(256) node1_kernel(
        const float* __restrict__ x,
        const float* __restrict__ root1,
        const float* __restrict__ bias1) {
    __shared__ float sx[8][16];
    int c = threadIdx.x;
    if (c < 32) ((float4*)sx)[c] = ((const float4*)x)[blockIdx.x * 32 + c];
    __syncthreads();
    int nl = c >> 5, o = c & 31;
    int idx = blockIdx.x * 256 + c;
    const float4* xk = (const float4*)sx[nl];
    float4 a0 = xk[0], a1 = xk[1], a2 = xk[2], a3 = xk[3];
    float xv[16] = {a0.x,a0.y,a0.z,a0.w, a1.x,a1.y,a1.z,a1.w,
                    a2.x,a2.y,a2.z,a2.w, a3.x,a3.y,a3.z,a3.w};
    float acc = g_agg1[idx] + bias1[o];
    #pragma unroll
    for (int i = 0; i < 16; i++) acc += xv[i] * root1[i * 32 + o];
    g_h1[idx] = fmaxf(acc, 0.f);
}

// ---------------------------------------------------------------------------
// Node update 2 + mean-pool accumulation; block = 16 nodes x 16 o
// sh needs 16*32 floats = 128 float4 -> only threads c<128 stage (BUGFIX R12:
// previously all 256 threads wrote -> shared OOB -> illegal memory access)
// ---------------------------------------------------------------------------
__global__ void __launch_bounds__(256) node2pool_kernel(
        const float* __restrict__ root2,
        const float* __restrict__ bias2,
        const int* __restrict__ batch) {
    __shared__ float sh[16][32];
    int c = threadIdx.x;
    if (c < 128) ((float4*)sh)[c] = ((const float4*)g_h1)[blockIdx.x * 128 + c];
    __syncthreads();
    int nl = c >> 4, o = c & 15;
    int idx = blockIdx.x * 256 + c;
    int n = blockIdx.x * 16 + nl;
    const float4* hk = (const float4*)sh[nl];
    float acc = g_agg2[idx] + bias2[o];
    #pragma unroll
    for (int q = 0; q < 8; q++) {
        float4 a = hk[q];
        acc += a.x * root2[(4*q)   * 16 + o];
        acc += a.y * root2[(4*q+1) * 16 + o];
        acc += a.z * root2[(4*q+2) * 16 + o];
        acc += a.w * root2[(4*q+3) * 16 + o];
    }
    float h = fmaxf(acc, 0.f);
    int g = batch[n];
    atomicAdd(&g_sums[g * 16 + o], h);
    if (o == 0) atomicAdd(&g_cnts[g], 1.0f);
}

// ---------------------------------------------------------------------------
// Readout MLP: 16 -> 8 (relu) -> 1
// ---------------------------------------------------------------------------
__global__ void readout_kernel(const float* __restrict__ lin1_w,
                               const float* __restrict__ lin1_b,
                               const float* __restrict__ lin2_w,
                               const float* __restrict__ lin2_b,
                               float* __restrict__ out) {
    int g = blockIdx.x * blockDim.x + threadIdx.x;
    if (g >= N_GRAPHS) return;
    float inv = 1.0f / fmaxf(g_cnts[g], 1.0f);
    float p[16];
    #pragma unroll
    for (int c = 0; c < 16; c++) p[c] = g_sums[g * 16 + c] * inv;
    float o = lin2_b[0];
    #pragma unroll
    for (int j = 0; j < 8; j++) {
        float z = lin1_b[j];
        #pragma unroll
        for (int c = 0; c < 16; c++) z += p[c] * lin1_w[c * 8 + j];
        o += fmaxf(z, 0.f) * lin2_w[j];
    }
    out[g] = o;
}

// ---------------------------------------------------------------------------
// Launch
// ---------------------------------------------------------------------------
extern "C" void kernel_launch(void* const* d_in, const int* in_sizes, int n_in,
                              void* d_out, int out_size) {
    const float* x         = (const float*)d_in[0];
    const float* edge_attr = (const float*)d_in[1];
    const int*   ei        = (const int*)  d_in[2];
    const int*   batch     = (const int*)  d_in[3];
    const float* nn1_w1    = (const float*)d_in[4];
    const float* nn1_b1    = (const float*)d_in[5];
    const float* nn1_w2    = (const float*)d_in[6];
    const float* nn1_b2    = (const float*)d_in[7];
    const float* root1     = (const float*)d_in[8];
    const float* bias1     = (const float*)d_in[9];
    const float* nn2_w1    = (const float*)d_in[10];
    const float* nn2_b1    = (const float*)d_in[11];
    const float* nn2_w2    = (const float*)d_in[12];
    const float* nn2_b2    = (const float*)d_in[13];
    const float* root2     = (const float*)d_in[14];
    const float* bias2     = (const float*)d_in[15];
    const float* lin1_w    = (const float*)d_in[16];
    const float* lin1_b    = (const float*)d_in[17];
    const float* lin2_w    = (const float*)d_in[18];
    const float* lin2_b    = (const float*)d_in[19];
    float* out = (float*)d_out;

    prep_kernel<<<1563, 256>>>(edge_attr, nn1_w1, nn1_b1, nn2_w1, nn2_b1);
    u1_kernel<<<640, 512>>>(x, nn1_w2, nn1_b2);
    edge1_kernel<<<N_EDGES / 8, 256>>>(ei);
    node1_kernel<<<N_NODES / 8, 256>>>(x, root1, bias1);
    u2_kernel<<<640, 256>>>(nn2_w2, nn2_b2);
    edge2_kernel<<<N_EDGES / 16, 256>>>(ei);
    node2pool_kernel<<<N_NODES / 16, 256>>>(root2, bias2, batch);
    readout_kernel<<<(N_GRAPHS + 255) / 256, 256>>>(lin1_w, lin1_b, lin2_w, lin2_b, out);
}